// round 1
// baseline (speedup 1.0000x reference)
#include <cuda_runtime.h>
#include <math.h>

// ---------------- problem constants ----------------
constexpr int N_ = 1024;
constexpr int H_ = 128;
constexpr int P_ = 523776;          // N*(N-1)/2
constexpr int TI = 32;              // pair tile dim
constexpr int NT = N_ / TI;         // 32 tiles per dim
constexpr int NBLK = NT * (NT + 1) / 2;  // 528 blocks over upper triangle

// ---------------- device scratch (no runtime allocs allowed) ----------------
__device__ float g_Uc[N_ * H_];
__device__ float g_Vc[N_ * H_];
__device__ float g_Ua[N_ * H_];
__device__ float g_Va[N_ * H_];

// ---------------- helpers ----------------
__device__ __forceinline__ float gelu_f(float x) {
    return 0.5f * x * (1.0f + erff(x * 0.70710678118654752440f));
}
__device__ __forceinline__ float sigmoid_f(float x) {
    return 1.0f / (1.0f + expf(-x));
}
// packed dual-FMA (Blackwell f32x2) — 2 FLOP-pairs per fma-pipe issue slot
__device__ __forceinline__ float2 ffma2(float2 a, float2 b, float2 c) {
    unsigned long long au = *reinterpret_cast<unsigned long long*>(&a);
    unsigned long long bu = *reinterpret_cast<unsigned long long*>(&b);
    unsigned long long cu = *reinterpret_cast<unsigned long long*>(&c);
    unsigned long long du;
    asm("fma.rn.f32x2 %0, %1, %2, %3;" : "=l"(du) : "l"(au), "l"(bu), "l"(cu));
    return *reinterpret_cast<float2*>(&du);
}

// ---------------- kernel 1: per-embedding first-layer precompute ----------------
// Uc[i] = e_i @ cW1[0:128]   + cb1 ;  Vc[j] = e_j @ cW1[128:256]
// Ua[i] = e_i @ aW1[0:128]   + ab1 ;  Va[j] = e_j @ aW1[128:256]
__global__ void __launch_bounds__(128) precompute_uv_kernel(
    const float* __restrict__ E, const float* __restrict__ cW1, const float* __restrict__ cb1,
    const float* __restrict__ aW1, const float* __restrict__ ab1)
{
    __shared__ float es[8][128];
    int i0 = blockIdx.x * 8;
    int t = threadIdx.x;
    for (int x = t; x < 8 * 128; x += 128) es[x >> 7][x & 127] = E[i0 * 128 + x];
    __syncthreads();

    float uc[8], vc[8], ua[8], va[8];
#pragma unroll
    for (int r = 0; r < 8; r++) { uc[r] = 0.f; vc[r] = 0.f; ua[r] = 0.f; va[r] = 0.f; }
    int k = t;
    for (int d = 0; d < 128; d++) {
        float wuc = cW1[d * 128 + k];
        float wvc = cW1[(d + 128) * 128 + k];
        float wua = aW1[d * 128 + k];
        float wva = aW1[(d + 128) * 128 + k];
#pragma unroll
        for (int r = 0; r < 8; r++) {
            float e = es[r][d];
            uc[r] = fmaf(e, wuc, uc[r]);
            vc[r] = fmaf(e, wvc, vc[r]);
            ua[r] = fmaf(e, wua, ua[r]);
            va[r] = fmaf(e, wva, va[r]);
        }
    }
    float bc = cb1[k], ba = ab1[k];
#pragma unroll
    for (int r = 0; r < 8; r++) {
        g_Uc[(i0 + r) * 128 + k] = uc[r] + bc;
        g_Vc[(i0 + r) * 128 + k] = vc[r];
        g_Ua[(i0 + r) * 128 + k] = ua[r] + ba;
        g_Va[(i0 + r) * 128 + k] = va[r];
    }
}

// ---------------- kernel 2: importance head (N rows) ----------------
__global__ void __launch_bounds__(64) imp_kernel(
    const float* __restrict__ E, const float* __restrict__ trace,
    const float* __restrict__ iW1, const float* __restrict__ ib1,
    const float* __restrict__ iW2, const float* __restrict__ ib2,
    float* __restrict__ outb)
{
    __shared__ float fin[133];
    __shared__ float red2[2];
    int i = blockIdx.x, t = threadIdx.x;
    fin[t] = E[i * 128 + t];
    fin[64 + t] = E[i * 128 + 64 + t];
    if (t < 5) fin[128 + t] = trace[i * 5 + t];
    __syncthreads();
    float acc = ib1[t];
    for (int d = 0; d < 133; d++) acc = fmaf(fin[d], iW1[d * 64 + t], acc);
    float part = gelu_f(acc) * iW2[t];
#pragma unroll
    for (int o = 16; o > 0; o >>= 1) part += __shfl_down_sync(0xffffffffu, part, o);
    if ((t & 31) == 0) red2[t >> 5] = part;
    __syncthreads();
    if (t == 0) outb[i] = sigmoid_f(red2[0] + red2[1] + ib2[0]);
}

// ---------------- kernel 3/4: fused pair MLP (cons: COLS=64+LN+GELU, assoc: COLS=32+ReLU) ----------------
template <int COLS, bool IS_CONS>
__global__ void __launch_bounds__(256, 1) pair_kernel(
    const float* __restrict__ W2g, const float* __restrict__ b2g,
    const float* __restrict__ w3g, const float* __restrict__ b3g,
    const float* __restrict__ lng, const float* __restrict__ lnb,
    float* __restrict__ outb)
{
    constexpr int CT = COLS / 8;   // cols per thread (8 or 4)
    constexpr int CP = CT / 2;     // float2 packs per thread (4 or 2)

    extern __shared__ float sm[];
    float* Ht   = sm;                    // [128][256] transposed hidden, 32768 f
    float* W2s  = sm + 32768;            // [128][COLS]
    float* red  = W2s + 128 * COLS;      // [8][256]
    float* Us   = red + 2048;            // [32][129] padded (bank-conflict-free)
    float* Vs   = Us + 32 * 129;         // [32][129]
    float* b2s  = Vs + 32 * 129;         // [COLS]
    float* w3s  = b2s + COLS;            // [COLS]
    float* lngs = w3s + COLS;            // [128]
    float* lnbs = lngs + 128;            // [128]

    int t = threadIdx.x;

    // decode blockIdx -> (ti, tj) with tj >= ti
    int rem = blockIdx.x, ti = 0;
    while (rem >= NT - ti) { rem -= NT - ti; ti++; }
    int tj = ti + rem;
    int I0 = ti * TI, J0 = tj * TI;

    const float* Ug = IS_CONS ? g_Uc : g_Ua;
    const float* Vg = IS_CONS ? g_Vc : g_Va;

    for (int x = t; x < 128 * COLS; x += 256) W2s[x] = W2g[x];
    if (t < COLS) { b2s[t] = b2g[t]; w3s[t] = w3g[t]; }
    if constexpr (IS_CONS) {
        if (t < 128) { lngs[t] = lng[t]; lnbs[t] = lnb[t]; }
    }
    for (int x = t; x < 32 * 128; x += 256) {
        int r = x >> 7, k = x & 127;
        Us[r * 129 + k] = Ug[(I0 + r) * 128 + k];
        Vs[r * 129 + k] = Vg[(J0 + r) * 128 + k];
    }
    float b3 = b3g[0];
    __syncthreads();

    int rg = t & 31, cg = t >> 5;

    // 4 chunks of 256 pairs (8 i-rows x 32 j) per 32x32 tile
    for (int cch = 0; cch < 4; cch++) {
        // ---- phase A: per-pair hidden vector -> Ht[k][slot] ----
        {
            const float* u = Us + (cch * 8 + (t >> 5)) * 129;  // broadcast within warp
            const float* v = Vs + (t & 31) * 129;              // conflict-free (stride 129)
            if constexpr (IS_CONS) {
                float s1 = 0.f, s2 = 0.f;
#pragma unroll 8
                for (int k = 0; k < 128; k++) {
                    float x = u[k] + v[k];
                    s1 += x; s2 = fmaf(x, x, s2);
                }
                float mean = s1 * 0.0078125f;
                float var  = s2 * 0.0078125f - mean * mean;
                float rstd = rsqrtf(var + 1e-5f);
#pragma unroll 4
                for (int k = 0; k < 128; k++) {
                    float x = u[k] + v[k];
                    float hn = fmaf((x - mean) * rstd, lngs[k], lnbs[k]);
                    Ht[k * 256 + t] = gelu_f(hn);
                }
            } else {
#pragma unroll 8
                for (int k = 0; k < 128; k++) {
                    float x = u[k] + v[k];
                    Ht[k * 256 + t] = fmaxf(x, 0.f);
                }
            }
        }
        __syncthreads();

        // ---- phase B: [256 x 128] @ [128 x COLS] register-blocked smem GEMM ----
        float2 acc[8][CP];
#pragma unroll
        for (int r = 0; r < 8; r++)
#pragma unroll
            for (int p = 0; p < CP; p++) acc[r][p] = make_float2(0.f, 0.f);

#pragma unroll 2
        for (int k = 0; k < 128; k++) {
            // rows split 0..127 / 128..255 -> consecutive-lane 16B chunks, conflict-free
            float4 h0 = *reinterpret_cast<const float4*>(Ht + k * 256 + rg * 4);
            float4 h1 = *reinterpret_cast<const float4*>(Ht + k * 256 + 128 + rg * 4);
            const float4* wp = reinterpret_cast<const float4*>(W2s + k * COLS + cg * CT);
            float hr[8] = {h0.x, h0.y, h0.z, h0.w, h1.x, h1.y, h1.z, h1.w};
            float2 wv[CP];
            {
                float4 wa = wp[0];
                wv[0] = make_float2(wa.x, wa.y);
                wv[1] = make_float2(wa.z, wa.w);
                if constexpr (CP == 4) {
                    float4 wb = wp[1];
                    wv[2] = make_float2(wb.x, wb.y);
                    wv[3] = make_float2(wb.z, wb.w);
                }
            }
#pragma unroll
            for (int r = 0; r < 8; r++) {
                float2 hh = make_float2(hr[r], hr[r]);
#pragma unroll
                for (int p = 0; p < CP; p++) acc[r][p] = ffma2(hh, wv[p], acc[r][p]);
            }
        }
        __syncthreads();

        // ---- epilogue: bias + activation + dot(w3) partials ----
#pragma unroll
        for (int r = 0; r < 8; r++) {
            int row = (r < 4) ? (rg * 4 + r) : (128 + rg * 4 + (r - 4));
            float pr = 0.f;
#pragma unroll
            for (int p = 0; p < CP; p++) {
                int c0 = cg * CT + 2 * p;
                float y0 = acc[r][p].x + b2s[c0];
                float y1 = acc[r][p].y + b2s[c0 + 1];
                if constexpr (IS_CONS) {
                    pr = fmaf(gelu_f(y0), w3s[c0], pr);
                    pr = fmaf(gelu_f(y1), w3s[c0 + 1], pr);
                } else {
                    pr = fmaf(fmaxf(y0, 0.f), w3s[c0], pr);
                    pr = fmaf(fmaxf(y1, 0.f), w3s[c0 + 1], pr);
                }
            }
            red[cg * 256 + row] = pr;
        }
        __syncthreads();

        // ---- final reduce over 8 col-groups + sigmoid + triu-packed store ----
        float logit = b3;
#pragma unroll
        for (int g = 0; g < 8; g++) logit += red[g * 256 + t];
        int di = cch * 8 + (t >> 5), dj = t & 31;
        int i = I0 + di, j = J0 + dj;
        if (i < j) {
            int p = i * (N_ - 1) - (i * (i - 1)) / 2 + (j - i - 1);
            outb[p] = sigmoid_f(logit);
        }
        __syncthreads();  // protect Ht/red for next chunk
    }
}

// ---------------- launch ----------------
extern "C" void kernel_launch(void* const* d_in, const int* in_sizes, int n_in,
                              void* d_out, int out_size)
{
    const float* E     = (const float*)d_in[0];
    const float* trace = (const float*)d_in[1];
    const float* cW1 = (const float*)d_in[2];
    const float* cb1 = (const float*)d_in[3];
    const float* lng = (const float*)d_in[4];
    const float* lnb = (const float*)d_in[5];
    const float* cW2 = (const float*)d_in[6];
    const float* cb2 = (const float*)d_in[7];
    const float* cW3 = (const float*)d_in[8];
    const float* cb3 = (const float*)d_in[9];
    const float* aW1 = (const float*)d_in[10];
    const float* ab1 = (const float*)d_in[11];
    const float* aW2 = (const float*)d_in[12];
    const float* ab2 = (const float*)d_in[13];
    const float* aW3 = (const float*)d_in[14];
    const float* ab3 = (const float*)d_in[15];
    const float* iW1 = (const float*)d_in[16];
    const float* ib1 = (const float*)d_in[17];
    const float* iW2 = (const float*)d_in[18];
    const float* ib2 = (const float*)d_in[19];
    float* out = (float*)d_out;

    constexpr int SMEM_CONS  = (32768 + 128 * 64 + 2048 + 2 * 32 * 129 + 2 * 64 + 256) * 4;
    constexpr int SMEM_ASSOC = (32768 + 128 * 32 + 2048 + 2 * 32 * 129 + 2 * 32 + 256) * 4;

    cudaFuncSetAttribute(pair_kernel<64, true>,  cudaFuncAttributeMaxDynamicSharedMemorySize, SMEM_CONS);
    cudaFuncSetAttribute(pair_kernel<32, false>, cudaFuncAttributeMaxDynamicSharedMemorySize, SMEM_ASSOC);

    precompute_uv_kernel<<<128, 128>>>(E, cW1, cb1, aW1, ab1);
    imp_kernel<<<N_, 64>>>(E, trace, iW1, ib1, iW2, ib2, out + 2 * P_);
    pair_kernel<64, true><<<NBLK, 256, SMEM_CONS>>>(cW2, cb2, cW3, cb3, lng, lnb, out);
    pair_kernel<32, false><<<NBLK, 256, SMEM_ASSOC>>>(aW2, ab2, aW3, ab3, nullptr, nullptr, out + P_);
}

// round 2
// speedup vs baseline: 1.2261x; 1.2261x over previous
#include <cuda_runtime.h>
#include <math.h>

// ---------------- problem constants ----------------
constexpr int N_ = 1024;
constexpr int H_ = 128;
constexpr int P_ = 523776;          // N*(N-1)/2
constexpr int TI = 32;              // pair tile dim
constexpr int NT = N_ / TI;         // 32 tiles per dim
constexpr int NBLK = NT * (NT + 1) / 2;  // 528 blocks over upper triangle
constexpr int UVS = 132;            // padded row stride for Us/Vs (float4-able, conflict-free)

// ---------------- device scratch (no runtime allocs allowed) ----------------
__device__ float g_Uc[N_ * H_];
__device__ float g_Vc[N_ * H_];
__device__ float g_Ua[N_ * H_];
__device__ float g_Va[N_ * H_];

// ---------------- helpers ----------------
__device__ __forceinline__ float gelu_f(float x) {
    return 0.5f * x * (1.0f + erff(x * 0.70710678118654752440f));
}
__device__ __forceinline__ float sigmoid_f(float x) {
    return 1.0f / (1.0f + expf(-x));
}
// packed dual-FMA (Blackwell f32x2) — 2 FMA per fma-pipe issue slot
__device__ __forceinline__ float2 ffma2(float2 a, float2 b, float2 c) {
    unsigned long long au = *reinterpret_cast<unsigned long long*>(&a);
    unsigned long long bu = *reinterpret_cast<unsigned long long*>(&b);
    unsigned long long cu = *reinterpret_cast<unsigned long long*>(&c);
    unsigned long long du;
    asm("fma.rn.f32x2 %0, %1, %2, %3;" : "=l"(du) : "l"(au), "l"(bu), "l"(cu));
    return *reinterpret_cast<float2*>(&du);
}

// ---------------- kernel 1: per-embedding first-layer precompute ----------------
__global__ void __launch_bounds__(128) precompute_uv_kernel(
    const float* __restrict__ E, const float* __restrict__ cW1, const float* __restrict__ cb1,
    const float* __restrict__ aW1, const float* __restrict__ ab1)
{
    __shared__ float es[8][128];
    int i0 = blockIdx.x * 8;
    int t = threadIdx.x;
    for (int x = t; x < 8 * 128; x += 128) es[x >> 7][x & 127] = E[i0 * 128 + x];
    __syncthreads();

    float uc[8], vc[8], ua[8], va[8];
#pragma unroll
    for (int r = 0; r < 8; r++) { uc[r] = 0.f; vc[r] = 0.f; ua[r] = 0.f; va[r] = 0.f; }
    int k = t;
    for (int d = 0; d < 128; d++) {
        float wuc = cW1[d * 128 + k];
        float wvc = cW1[(d + 128) * 128 + k];
        float wua = aW1[d * 128 + k];
        float wva = aW1[(d + 128) * 128 + k];
#pragma unroll
        for (int r = 0; r < 8; r++) {
            float e = es[r][d];
            uc[r] = fmaf(e, wuc, uc[r]);
            vc[r] = fmaf(e, wvc, vc[r]);
            ua[r] = fmaf(e, wua, ua[r]);
            va[r] = fmaf(e, wva, va[r]);
        }
    }
    float bc = cb1[k], ba = ab1[k];
#pragma unroll
    for (int r = 0; r < 8; r++) {
        g_Uc[(i0 + r) * 128 + k] = uc[r] + bc;
        g_Vc[(i0 + r) * 128 + k] = vc[r];
        g_Ua[(i0 + r) * 128 + k] = ua[r] + ba;
        g_Va[(i0 + r) * 128 + k] = va[r];
    }
}

// ---------------- kernel 2: importance head (N rows) ----------------
__global__ void __launch_bounds__(64) imp_kernel(
    const float* __restrict__ E, const float* __restrict__ trace,
    const float* __restrict__ iW1, const float* __restrict__ ib1,
    const float* __restrict__ iW2, const float* __restrict__ ib2,
    float* __restrict__ outb)
{
    __shared__ float fin[133];
    __shared__ float red2[2];
    int i = blockIdx.x, t = threadIdx.x;
    fin[t] = E[i * 128 + t];
    fin[64 + t] = E[i * 128 + 64 + t];
    if (t < 5) fin[128 + t] = trace[i * 5 + t];
    __syncthreads();
    float acc = ib1[t];
    for (int d = 0; d < 133; d++) acc = fmaf(fin[d], iW1[d * 64 + t], acc);
    float part = gelu_f(acc) * iW2[t];
#pragma unroll
    for (int o = 16; o > 0; o >>= 1) part += __shfl_down_sync(0xffffffffu, part, o);
    if ((t & 31) == 0) red2[t >> 5] = part;
    __syncthreads();
    if (t == 0) outb[i] = sigmoid_f(red2[0] + red2[1] + ib2[0]);
}

// ---------------- kernel 3/4: fused pair MLP ----------------
// 512 threads. Per 32x32 (i,j) tile, 4 chunks of 256 pairs.
// Phase A: 2 threads per pair (split-K 64 each), vectorized float4 loads.
// Phase B: [256x128]@[128xCOLS] register-blocked GEMM, R=4 rows x C cols/thread.
template <int COLS, bool IS_CONS>
__global__ void __launch_bounds__(512, 1) pair_kernel(
    const float* __restrict__ W2g, const float* __restrict__ b2g,
    const float* __restrict__ w3g, const float* __restrict__ b3g,
    const float* __restrict__ lng, const float* __restrict__ lnb,
    float* __restrict__ outb)
{
    constexpr int C  = IS_CONS ? 8 : 4;   // cols per thread
    constexpr int CP = C / 2;             // float2 packs per thread

    extern __shared__ float sm[];
    float* Ht   = sm;                    // [128][256] transposed hidden
    float* W2s  = sm + 32768;            // [128][COLS]
    float* red  = W2s + 128 * COLS;      // [8][256] (also LN-stats scratch)
    float* Us   = red + 2048;            // [32][132]
    float* Vs   = Us + 32 * UVS;         // [32][132]
    float* b2s  = Vs + 32 * UVS;         // [COLS]
    float* w3s  = b2s + COLS;            // [COLS]
    float* lngs = w3s + COLS;            // [128]
    float* lnbs = lngs + 128;            // [128]

    int t = threadIdx.x;

    // decode blockIdx -> (ti, tj) with tj >= ti
    int rem = blockIdx.x, ti = 0;
    while (rem >= NT - ti) { rem -= NT - ti; ti++; }
    int tj = ti + rem;
    int I0 = ti * TI, J0 = tj * TI;

    const float* Ug = IS_CONS ? g_Uc : g_Ua;
    const float* Vg = IS_CONS ? g_Vc : g_Va;

    for (int x = t; x < 128 * COLS; x += 512) W2s[x] = W2g[x];
    if (t < COLS) { b2s[t] = b2g[t]; w3s[t] = w3g[t]; }
    if constexpr (IS_CONS) {
        if (t >= 256 && t < 384) { lngs[t - 256] = lng[t - 256]; lnbs[t - 256] = lnb[t - 256]; }
    }
    for (int x = t; x < 32 * 128; x += 512) {
        int r = x >> 7, k = x & 127;
        Us[r * UVS + k] = Ug[(I0 + r) * 128 + k];
        Vs[r * UVS + k] = Vg[(J0 + r) * 128 + k];
    }
    float b3 = b3g[0];
    __syncthreads();

    // phase A decomposition: pair p = t & 255, k-half = t >> 8
    int p    = t & 255;
    int half = t >> 8;
    int k0   = half * 64;

    // phase B decomposition
    int rg = t & 63;   // 4 rows: rg*4 .. rg*4+3
    int cg = t >> 6;   // 8 col groups of C cols

    for (int cch = 0; cch < 4; cch++) {
        const float* u = Us + (cch * 8 + (p >> 5)) * UVS + k0;
        const float* v = Vs + (p & 31) * UVS + k0;

        // ---- phase A ----
        if constexpr (IS_CONS) {
            float s1 = 0.f, s2 = 0.f;
#pragma unroll
            for (int kk = 0; kk < 64; kk += 4) {
                float4 uu = *reinterpret_cast<const float4*>(u + kk);
                float4 vv = *reinterpret_cast<const float4*>(v + kk);
                float x0 = uu.x + vv.x, x1 = uu.y + vv.y, x2 = uu.z + vv.z, x3 = uu.w + vv.w;
                s1 += (x0 + x1) + (x2 + x3);
                s2 = fmaf(x0, x0, s2); s2 = fmaf(x1, x1, s2);
                s2 = fmaf(x2, x2, s2); s2 = fmaf(x3, x3, s2);
            }
            red[half * 512 + p]       = s1;
            red[half * 512 + 256 + p] = s2;
            __syncthreads();
            float s1t = red[p] + red[512 + p];
            float s2t = red[256 + p] + red[768 + p];
            float mean = s1t * 0.0078125f;
            float var  = s2t * 0.0078125f - mean * mean;
            float rstd = rsqrtf(var + 1e-5f);
#pragma unroll
            for (int kk = 0; kk < 64; kk += 4) {
                float4 uu = *reinterpret_cast<const float4*>(u + kk);
                float4 vv = *reinterpret_cast<const float4*>(v + kk);
                float xs[4] = {uu.x + vv.x, uu.y + vv.y, uu.z + vv.z, uu.w + vv.w};
#pragma unroll
                for (int i2 = 0; i2 < 4; i2++) {
                    int k = k0 + kk + i2;
                    float hn = fmaf((xs[i2] - mean) * rstd, lngs[k], lnbs[k]);
                    Ht[k * 256 + p] = gelu_f(hn);
                }
            }
        } else {
#pragma unroll
            for (int kk = 0; kk < 64; kk += 4) {
                float4 uu = *reinterpret_cast<const float4*>(u + kk);
                float4 vv = *reinterpret_cast<const float4*>(v + kk);
                float xs[4] = {uu.x + vv.x, uu.y + vv.y, uu.z + vv.z, uu.w + vv.w};
#pragma unroll
                for (int i2 = 0; i2 < 4; i2++)
                    Ht[(k0 + kk + i2) * 256 + p] = fmaxf(xs[i2], 0.f);
            }
        }
        __syncthreads();

        // ---- phase B: register-blocked smem GEMM ----
        float2 acc[4][CP];
#pragma unroll
        for (int r = 0; r < 4; r++)
#pragma unroll
            for (int q = 0; q < CP; q++) acc[r][q] = make_float2(0.f, 0.f);

#pragma unroll 2
        for (int k = 0; k < 128; k++) {
            float4 h = *reinterpret_cast<const float4*>(Ht + k * 256 + rg * 4);
            const float4* wp = reinterpret_cast<const float4*>(W2s + k * COLS + cg * C);
            float2 wv[CP];
            {
                float4 wa = wp[0];
                wv[0] = make_float2(wa.x, wa.y);
                wv[1] = make_float2(wa.z, wa.w);
                if constexpr (CP == 4) {
                    float4 wb = wp[1];
                    wv[2] = make_float2(wb.x, wb.y);
                    wv[3] = make_float2(wb.z, wb.w);
                }
            }
            float hr[4] = {h.x, h.y, h.z, h.w};
#pragma unroll
            for (int r = 0; r < 4; r++) {
                float2 hh = make_float2(hr[r], hr[r]);
#pragma unroll
                for (int q = 0; q < CP; q++) acc[r][q] = ffma2(hh, wv[q], acc[r][q]);
            }
        }
        __syncthreads();

        // ---- epilogue: bias + activation + dot(w3) partials ----
#pragma unroll
        for (int r = 0; r < 4; r++) {
            int row = rg * 4 + r;
            float pr = 0.f;
#pragma unroll
            for (int q = 0; q < CP; q++) {
                int c0 = cg * C + 2 * q;
                float y0 = acc[r][q].x + b2s[c0];
                float y1 = acc[r][q].y + b2s[c0 + 1];
                if constexpr (IS_CONS) {
                    pr = fmaf(gelu_f(y0), w3s[c0], pr);
                    pr = fmaf(gelu_f(y1), w3s[c0 + 1], pr);
                } else {
                    pr = fmaf(fmaxf(y0, 0.f), w3s[c0], pr);
                    pr = fmaf(fmaxf(y1, 0.f), w3s[c0 + 1], pr);
                }
            }
            red[cg * 256 + row] = pr;
        }
        __syncthreads();

        // ---- final reduce + sigmoid + triu-packed store ----
        if (t < 256) {
            float logit = b3;
#pragma unroll
            for (int g = 0; g < 8; g++) logit += red[g * 256 + t];
            int i = I0 + cch * 8 + (t >> 5), j = J0 + (t & 31);
            if (i < j) {
                int pidx = i * (N_ - 1) - (i * (i - 1)) / 2 + (j - i - 1);
                outb[pidx] = sigmoid_f(logit);
            }
        }
        __syncthreads();  // protect Ht/red for next chunk
    }
}

// ---------------- launch ----------------
extern "C" void kernel_launch(void* const* d_in, const int* in_sizes, int n_in,
                              void* d_out, int out_size)
{
    const float* E     = (const float*)d_in[0];
    const float* trace = (const float*)d_in[1];
    const float* cW1 = (const float*)d_in[2];
    const float* cb1 = (const float*)d_in[3];
    const float* lng = (const float*)d_in[4];
    const float* lnb = (const float*)d_in[5];
    const float* cW2 = (const float*)d_in[6];
    const float* cb2 = (const float*)d_in[7];
    const float* cW3 = (const float*)d_in[8];
    const float* cb3 = (const float*)d_in[9];
    const float* aW1 = (const float*)d_in[10];
    const float* ab1 = (const float*)d_in[11];
    const float* aW2 = (const float*)d_in[12];
    const float* ab2 = (const float*)d_in[13];
    const float* aW3 = (const float*)d_in[14];
    const float* ab3 = (const float*)d_in[15];
    const float* iW1 = (const float*)d_in[16];
    const float* ib1 = (const float*)d_in[17];
    const float* iW2 = (const float*)d_in[18];
    const float* ib2 = (const float*)d_in[19];
    float* out = (float*)d_out;

    constexpr int SMEM_CONS  = (32768 + 128 * 64 + 2048 + 2 * 32 * UVS + 2 * 64 + 256) * 4;
    constexpr int SMEM_ASSOC = (32768 + 128 * 32 + 2048 + 2 * 32 * UVS + 2 * 32) * 4;

    cudaFuncSetAttribute(pair_kernel<64, true>,  cudaFuncAttributeMaxDynamicSharedMemorySize, SMEM_CONS);
    cudaFuncSetAttribute(pair_kernel<32, false>, cudaFuncAttributeMaxDynamicSharedMemorySize, SMEM_ASSOC);

    precompute_uv_kernel<<<128, 128>>>(E, cW1, cb1, aW1, ab1);
    imp_kernel<<<N_, 64>>>(E, trace, iW1, ib1, iW2, ib2, out + 2 * P_);
    pair_kernel<64, true><<<NBLK, 512, SMEM_CONS>>>(cW2, cb2, cW3, cb3, lng, lnb, out);
    pair_kernel<32, false><<<NBLK, 512, SMEM_ASSOC>>>(aW2, ab2, aW3, ab3, nullptr, nullptr, out + P_);
}

// round 3
// speedup vs baseline: 1.3387x; 1.0919x over previous
#include <cuda_runtime.h>
#include <math.h>

// ---------------- problem constants ----------------
constexpr int N_ = 1024;
constexpr int H_ = 128;
constexpr int P_ = 523776;          // N*(N-1)/2
constexpr int TI = 32;              // pair tile dim
constexpr int NT = N_ / TI;         // 32 tiles per dim
constexpr int NBLK = NT * (NT + 1) / 2;  // 528 blocks over upper triangle
constexpr int UVS = 132;            // padded row stride for Us/Vs (float4-able, conflict-free)

// smem layout (floats)
constexpr int OFF_HT  = 0;                    // [128][256]
constexpr int OFF_W2  = 32768;                // [128][64] max
constexpr int OFF_RED = OFF_W2 + 8192;        // [2048]
constexpr int OFF_US  = OFF_RED + 2048;       // [32][132]
constexpr int OFF_VS  = OFF_US + 32 * UVS;    // [32][132]
constexpr int OFF_B2  = OFF_VS + 32 * UVS;    // [64]
constexpr int OFF_W3  = OFF_B2 + 64;          // [64]
constexpr int OFF_LNG = OFF_W3 + 64;          // [128]
constexpr int OFF_LNB = OFF_LNG + 128;        // [128]
constexpr int SMEM_FLOATS = OFF_LNB + 128;
constexpr int SMEM_BYTES = SMEM_FLOATS * 4;   // ~207 KB

// ---------------- device scratch (no runtime allocs allowed) ----------------
__device__ float g_Uc[N_ * H_];
__device__ float g_Vc[N_ * H_];
__device__ float g_Ua[N_ * H_];
__device__ float g_Va[N_ * H_];

// ---------------- helpers ----------------
__device__ __forceinline__ float gelu_f(float x) {
    return 0.5f * x * (1.0f + erff(x * 0.70710678118654752440f));
}
__device__ __forceinline__ float sigmoid_f(float x) {
    return 1.0f / (1.0f + expf(-x));
}
// packed dual-FMA (Blackwell f32x2)
__device__ __forceinline__ float2 ffma2(float2 a, float2 b, float2 c) {
    unsigned long long au = *reinterpret_cast<unsigned long long*>(&a);
    unsigned long long bu = *reinterpret_cast<unsigned long long*>(&b);
    unsigned long long cu = *reinterpret_cast<unsigned long long*>(&c);
    unsigned long long du;
    asm("fma.rn.f32x2 %0, %1, %2, %3;" : "=l"(du) : "l"(au), "l"(bu), "l"(cu));
    return *reinterpret_cast<float2*>(&du);
}

// ---------------- kernel 1: per-embedding first-layer precompute ----------------
__global__ void __launch_bounds__(128) precompute_uv_kernel(
    const float* __restrict__ E, const float* __restrict__ cW1, const float* __restrict__ cb1,
    const float* __restrict__ aW1, const float* __restrict__ ab1)
{
    __shared__ float es[8][128];
    int i0 = blockIdx.x * 8;
    int t = threadIdx.x;
    for (int x = t; x < 8 * 128; x += 128) es[x >> 7][x & 127] = E[i0 * 128 + x];
    __syncthreads();

    float uc[8], vc[8], ua[8], va[8];
#pragma unroll
    for (int r = 0; r < 8; r++) { uc[r] = 0.f; vc[r] = 0.f; ua[r] = 0.f; va[r] = 0.f; }
    int k = t;
    for (int d = 0; d < 128; d++) {
        float wuc = cW1[d * 128 + k];
        float wvc = cW1[(d + 128) * 128 + k];
        float wua = aW1[d * 128 + k];
        float wva = aW1[(d + 128) * 128 + k];
#pragma unroll
        for (int r = 0; r < 8; r++) {
            float e = es[r][d];
            uc[r] = fmaf(e, wuc, uc[r]);
            vc[r] = fmaf(e, wvc, vc[r]);
            ua[r] = fmaf(e, wua, ua[r]);
            va[r] = fmaf(e, wva, va[r]);
        }
    }
    float bc = cb1[k], ba = ab1[k];
#pragma unroll
    for (int r = 0; r < 8; r++) {
        g_Uc[(i0 + r) * 128 + k] = uc[r] + bc;
        g_Vc[(i0 + r) * 128 + k] = vc[r];
        g_Ua[(i0 + r) * 128 + k] = ua[r] + ba;
        g_Va[(i0 + r) * 128 + k] = va[r];
    }
}

// ---------------- kernel 2: importance head (N rows) ----------------
__global__ void __launch_bounds__(64) imp_kernel(
    const float* __restrict__ E, const float* __restrict__ trace,
    const float* __restrict__ iW1, const float* __restrict__ ib1,
    const float* __restrict__ iW2, const float* __restrict__ ib2,
    float* __restrict__ outb)
{
    __shared__ float fin[133];
    __shared__ float red2[2];
    int i = blockIdx.x, t = threadIdx.x;
    fin[t] = E[i * 128 + t];
    fin[64 + t] = E[i * 128 + 64 + t];
    if (t < 5) fin[128 + t] = trace[i * 5 + t];
    __syncthreads();
    float acc = ib1[t];
    for (int d = 0; d < 133; d++) acc = fmaf(fin[d], iW1[d * 64 + t], acc);
    float part = gelu_f(acc) * iW2[t];
#pragma unroll
    for (int o = 16; o > 0; o >>= 1) part += __shfl_down_sync(0xffffffffu, part, o);
    if ((t & 31) == 0) red2[t >> 5] = part;
    __syncthreads();
    if (t == 0) outb[i] = sigmoid_f(red2[0] + red2[1] + ib2[0]);
}

// ---------------- fused pair MLP body ----------------
// 512 threads. Phase A: 2 threads/pair (split-K 64). Phase B: 256 threads,
// R=4 rows x C cols/thread, 4 col groups (h amp = 4).
template <int COLS, bool IS_CONS>
__device__ __forceinline__ void pair_body(
    int bid, float* sm,
    const float* __restrict__ Ug, const float* __restrict__ Vg,
    const float* __restrict__ W2g, const float* __restrict__ b2g,
    const float* __restrict__ w3g, const float* __restrict__ b3g,
    const float* __restrict__ lng, const float* __restrict__ lnb,
    float* __restrict__ outb)
{
    constexpr int C  = COLS / 4;   // cols per thread (16 cons / 8 assoc)
    constexpr int CP = C / 2;      // float2 packs (8 / 4)

    float* Ht   = sm + OFF_HT;
    float* W2s  = sm + OFF_W2;
    float* red  = sm + OFF_RED;
    float* Us   = sm + OFF_US;
    float* Vs   = sm + OFF_VS;
    float* b2s  = sm + OFF_B2;
    float* w3s  = sm + OFF_W3;
    float* lngs = sm + OFF_LNG;
    float* lnbs = sm + OFF_LNB;

    int t = threadIdx.x;

    // decode bid -> (ti, tj) with tj >= ti
    int rem = bid, ti = 0;
    while (rem >= NT - ti) { rem -= NT - ti; ti++; }
    int tj = ti + rem;
    int I0 = ti * TI, J0 = tj * TI;

    for (int x = t; x < 128 * COLS; x += 512) W2s[x] = W2g[x];
    if (t < COLS) { b2s[t] = b2g[t]; w3s[t] = w3g[t]; }
    if constexpr (IS_CONS) {
        if (t >= 256 && t < 384) { lngs[t - 256] = lng[t - 256]; lnbs[t - 256] = lnb[t - 256]; }
    }
    for (int x = t; x < 32 * 128; x += 512) {
        int r = x >> 7, k = x & 127;
        Us[r * UVS + k] = Ug[(I0 + r) * 128 + k];
        Vs[r * UVS + k] = Vg[(J0 + r) * 128 + k];
    }
    float b3 = b3g[0];
    __syncthreads();

    // phase A decomposition
    int p    = t & 255;
    int half = t >> 8;
    int k0   = half * 64;

    // phase B decomposition (t < 256 only)
    int rg = t & 63;   // rows rg*4 .. rg*4+3
    int cg = t >> 6;   // 4 col groups of C cols (only valid for t<256)

    for (int cch = 0; cch < 4; cch++) {
        const float* u = Us + (cch * 8 + (p >> 5)) * UVS + k0;
        const float* v = Vs + (p & 31) * UVS + k0;

        // ---- phase A ----
        if constexpr (IS_CONS) {
            float4 xv[16];
            float s1 = 0.f, s2 = 0.f;
#pragma unroll
            for (int kk = 0; kk < 16; kk++) {
                float4 uu = *reinterpret_cast<const float4*>(u + kk * 4);
                float4 vv = *reinterpret_cast<const float4*>(v + kk * 4);
                float4 x;
                x.x = uu.x + vv.x; x.y = uu.y + vv.y;
                x.z = uu.z + vv.z; x.w = uu.w + vv.w;
                xv[kk] = x;
                s1 += (x.x + x.y) + (x.z + x.w);
                s2 = fmaf(x.x, x.x, s2); s2 = fmaf(x.y, x.y, s2);
                s2 = fmaf(x.z, x.z, s2); s2 = fmaf(x.w, x.w, s2);
            }
            red[half * 512 + p]       = s1;
            red[half * 512 + 256 + p] = s2;
            __syncthreads();
            float s1t = red[p] + red[512 + p];
            float s2t = red[256 + p] + red[768 + p];
            float mean = s1t * 0.0078125f;
            float var  = s2t * 0.0078125f - mean * mean;
            float rstd = rsqrtf(var + 1e-5f);
#pragma unroll
            for (int kk = 0; kk < 16; kk++) {
                float xs[4] = {xv[kk].x, xv[kk].y, xv[kk].z, xv[kk].w};
#pragma unroll
                for (int i2 = 0; i2 < 4; i2++) {
                    int k = k0 + kk * 4 + i2;
                    float hn = fmaf((xs[i2] - mean) * rstd, lngs[k], lnbs[k]);
                    Ht[k * 256 + p] = gelu_f(hn);
                }
            }
        } else {
#pragma unroll
            for (int kk = 0; kk < 16; kk++) {
                float4 uu = *reinterpret_cast<const float4*>(u + kk * 4);
                float4 vv = *reinterpret_cast<const float4*>(v + kk * 4);
                float xs[4] = {uu.x + vv.x, uu.y + vv.y, uu.z + vv.z, uu.w + vv.w};
#pragma unroll
                for (int i2 = 0; i2 < 4; i2++)
                    Ht[(k0 + kk * 4 + i2) * 256 + p] = fmaxf(xs[i2], 0.f);
            }
        }
        __syncthreads();

        // ---- phase B: 256 threads, register-blocked smem GEMM ----
        if (t < 256) {
            float2 acc[4][CP];
#pragma unroll
            for (int r = 0; r < 4; r++)
#pragma unroll
                for (int q = 0; q < CP; q++) acc[r][q] = make_float2(0.f, 0.f);

            const float* wbase = W2s + cg * C;
#pragma unroll 2
            for (int k = 0; k < 128; k++) {
                float4 h = *reinterpret_cast<const float4*>(Ht + k * 256 + rg * 4);
                const float4* wp = reinterpret_cast<const float4*>(wbase + k * COLS);
                float2 wv[CP];
#pragma unroll
                for (int q4 = 0; q4 < CP / 2; q4++) {
                    float4 wa = wp[q4];
                    wv[2 * q4]     = make_float2(wa.x, wa.y);
                    wv[2 * q4 + 1] = make_float2(wa.z, wa.w);
                }
                float hr[4] = {h.x, h.y, h.z, h.w};
#pragma unroll
                for (int r = 0; r < 4; r++) {
                    float2 hh = make_float2(hr[r], hr[r]);
#pragma unroll
                    for (int q = 0; q < CP; q++) acc[r][q] = ffma2(hh, wv[q], acc[r][q]);
                }
            }

            // ---- epilogue: bias + activation + dot(w3) partials ----
#pragma unroll
            for (int r = 0; r < 4; r++) {
                int row = rg * 4 + r;
                float pr = 0.f;
#pragma unroll
                for (int q = 0; q < CP; q++) {
                    int c0 = cg * C + 2 * q;
                    float y0 = acc[r][q].x + b2s[c0];
                    float y1 = acc[r][q].y + b2s[c0 + 1];
                    if constexpr (IS_CONS) {
                        pr = fmaf(gelu_f(y0), w3s[c0], pr);
                        pr = fmaf(gelu_f(y1), w3s[c0 + 1], pr);
                    } else {
                        pr = fmaf(fmaxf(y0, 0.f), w3s[c0], pr);
                        pr = fmaf(fmaxf(y1, 0.f), w3s[c0 + 1], pr);
                    }
                }
                red[cg * 256 + row] = pr;
            }
        }
        __syncthreads();

        // ---- final reduce + sigmoid + triu-packed store ----
        if (t < 256) {
            float logit = b3 + ((red[t] + red[256 + t]) + (red[512 + t] + red[768 + t]));
            int i = I0 + cch * 8 + (t >> 5), j = J0 + (t & 31);
            if (i < j) {
                int pidx = i * (N_ - 1) - (i * (i - 1)) / 2 + (j - i - 1);
                outb[pidx] = sigmoid_f(logit);
            }
        }
        __syncthreads();  // protect Ht/red for next chunk
    }
}

// ---------------- fused kernel: cons blocks [0,528), assoc blocks [528,1056) ----------------
__global__ void __launch_bounds__(512, 1) pair_fused_kernel(
    const float* __restrict__ cW2, const float* __restrict__ cb2,
    const float* __restrict__ cW3, const float* __restrict__ cb3,
    const float* __restrict__ lng, const float* __restrict__ lnb,
    const float* __restrict__ aW2, const float* __restrict__ ab2,
    const float* __restrict__ aW3, const float* __restrict__ ab3,
    float* __restrict__ outb)
{
    extern __shared__ float sm[];
    if (blockIdx.x < NBLK) {
        pair_body<64, true>(blockIdx.x, sm, g_Uc, g_Vc, cW2, cb2, cW3, cb3, lng, lnb, outb);
    } else {
        pair_body<32, false>(blockIdx.x - NBLK, sm, g_Ua, g_Va, aW2, ab2, aW3, ab3,
                             nullptr, nullptr, outb + P_);
    }
}

// ---------------- launch ----------------
extern "C" void kernel_launch(void* const* d_in, const int* in_sizes, int n_in,
                              void* d_out, int out_size)
{
    const float* E     = (const float*)d_in[0];
    const float* trace = (const float*)d_in[1];
    const float* cW1 = (const float*)d_in[2];
    const float* cb1 = (const float*)d_in[3];
    const float* lng = (const float*)d_in[4];
    const float* lnb = (const float*)d_in[5];
    const float* cW2 = (const float*)d_in[6];
    const float* cb2 = (const float*)d_in[7];
    const float* cW3 = (const float*)d_in[8];
    const float* cb3 = (const float*)d_in[9];
    const float* aW1 = (const float*)d_in[10];
    const float* ab1 = (const float*)d_in[11];
    const float* aW2 = (const float*)d_in[12];
    const float* ab2 = (const float*)d_in[13];
    const float* aW3 = (const float*)d_in[14];
    const float* ab3 = (const float*)d_in[15];
    const float* iW1 = (const float*)d_in[16];
    const float* ib1 = (const float*)d_in[17];
    const float* iW2 = (const float*)d_in[18];
    const float* ib2 = (const float*)d_in[19];
    float* out = (float*)d_out;

    cudaFuncSetAttribute(pair_fused_kernel, cudaFuncAttributeMaxDynamicSharedMemorySize, SMEM_BYTES);

    precompute_uv_kernel<<<128, 128>>>(E, cW1, cb1, aW1, ab1);
    imp_kernel<<<N_, 64>>>(E, trace, iW1, ib1, iW2, ib2, out + 2 * P_);
    pair_fused_kernel<<<2 * NBLK, 512, SMEM_BYTES>>>(
        cW2, cb2, cW3, cb3, lng, lnb, aW2, ab2, aW3, ab3, out);
}

// round 4
// speedup vs baseline: 1.3710x; 1.0241x over previous
#include <cuda_runtime.h>
#include <math.h>

// ---------------- problem constants ----------------
constexpr int N_ = 1024;
constexpr int H_ = 128;
constexpr int P_ = 523776;          // N*(N-1)/2
constexpr int TI = 32;              // pair tile dim
constexpr int NT = N_ / TI;         // 32 tiles per dim
constexpr int NBLK = NT * (NT + 1) / 2;  // 528 blocks over upper triangle
constexpr int UVS = 132;            // padded row stride for Us/Vs

// pair-kernel smem layout (floats)
constexpr int OFF_HT  = 0;                    // [128][256]
constexpr int OFF_W2  = 32768;                // [128][64] max
constexpr int OFF_RED = OFF_W2 + 8192;        // [2048]
constexpr int OFF_US  = OFF_RED + 2048;       // [32][132]
constexpr int OFF_VS  = OFF_US + 32 * UVS;    // [32][132]
constexpr int OFF_B2  = OFF_VS + 32 * UVS;    // [64]
constexpr int OFF_W3  = OFF_B2 + 64;          // [64]
constexpr int OFF_LNG = OFF_W3 + 64;          // [128]
constexpr int OFF_LNB = OFF_LNG + 128;        // [128]
constexpr int SMEM_FLOATS = OFF_LNB + 128;
constexpr int SMEM_BYTES = SMEM_FLOATS * 4;   // ~207 KB

// precompute-kernel smem (floats)
constexpr int PRE_ES_STRIDE = 132;            // [64][132]
constexpr int PRE_WS_STRIDE = 68;             // [128][68]
constexpr int PRE_OFF_WS = 64 * PRE_ES_STRIDE;
constexpr int PRE_SMEM_BYTES = (PRE_OFF_WS + 128 * PRE_WS_STRIDE) * 4;  // ~68 KB

// ---------------- device scratch ----------------
__device__ float g_Uc[N_ * H_];
__device__ float g_Vc[N_ * H_];
__device__ float g_Ua[N_ * H_];
__device__ float g_Va[N_ * H_];

// ---------------- helpers ----------------
__device__ __forceinline__ float gelu_f(float x) {
    return 0.5f * x * (1.0f + erff(x * 0.70710678118654752440f));
}
__device__ __forceinline__ float sigmoid_f(float x) {
    return 1.0f / (1.0f + expf(-x));
}
__device__ __forceinline__ float2 ffma2(float2 a, float2 b, float2 c) {
    unsigned long long au = *reinterpret_cast<unsigned long long*>(&a);
    unsigned long long bu = *reinterpret_cast<unsigned long long*>(&b);
    unsigned long long cu = *reinterpret_cast<unsigned long long*>(&c);
    unsigned long long du;
    asm("fma.rn.f32x2 %0, %1, %2, %3;" : "=l"(du) : "l"(au), "l"(bu), "l"(cu));
    return *reinterpret_cast<float2*>(&du);
}

// ---------------- kernel 1: precompute as tiled GEMM ----------------
// O[1024, 512] = E[1024,128] @ Wgather[128,512]; arrays: 0=Uc 1=Vc 2=Ua 3=Va.
// grid = 16 rowTiles x 8 colTiles = 128 CTAs, 256 threads, 64x64 output tile.
__global__ void __launch_bounds__(256) precompute_gemm_kernel(
    const float* __restrict__ E,
    const float* __restrict__ cW1, const float* __restrict__ cb1,
    const float* __restrict__ aW1, const float* __restrict__ ab1)
{
    extern __shared__ float psm[];
    float* Es = psm;                 // [64][132]  (natural [r][k])
    float* Ws = psm + PRE_OFF_WS;    // [128][68]  ([k][c])

    int rowTile = blockIdx.x >> 3;   // 0..15
    int colTile = blockIdx.x & 7;    // 0..7
    int arr = colTile >> 1;          // 0..3
    int c0 = (colTile & 1) * 64;
    int r0 = rowTile * 64;

    const float* Wsrc = (arr < 2) ? cW1 : aW1;
    int doff = (arr & 1) ? 128 : 0;  // Vc/Va use rows 128..255

    int t = threadIdx.x;

    // load E tile [64][128] -> Es natural layout, float4 coalesced
    for (int x = t; x < 64 * 32; x += 256) {
        int r = x >> 5, k4 = x & 31;
        float4 e = *reinterpret_cast<const float4*>(E + (r0 + r) * 128 + k4 * 4);
        *reinterpret_cast<float4*>(Es + r * PRE_ES_STRIDE + k4 * 4) = e;
    }
    // load W tile [128][64]
    for (int x = t; x < 128 * 16; x += 256) {
        int d = x >> 4, c4 = x & 15;
        float4 w = *reinterpret_cast<const float4*>(Wsrc + (doff + d) * 128 + c0 + c4 * 4);
        *reinterpret_cast<float4*>(Ws + d * PRE_WS_STRIDE + c4 * 4) = w;
    }
    __syncthreads();

    // thread tile: 4 rows x 4 cols.  cgr fast -> w float4 reads conflict-free,
    // e reads warp-broadcast.
    int cgr = t & 15;     // col group
    int rg  = t >> 4;     // row group
    float acc[4][4] = {};

#pragma unroll 4
    for (int k = 0; k < 128; k += 4) {
        float4 ev[4], wv[4];
#pragma unroll
        for (int i = 0; i < 4; i++)
            ev[i] = *reinterpret_cast<const float4*>(Es + (rg * 4 + i) * PRE_ES_STRIDE + k);
#pragma unroll
        for (int kk = 0; kk < 4; kk++)
            wv[kk] = *reinterpret_cast<const float4*>(Ws + (k + kk) * PRE_WS_STRIDE + cgr * 4);
#pragma unroll
        for (int i = 0; i < 4; i++) {
            float er[4] = {ev[i].x, ev[i].y, ev[i].z, ev[i].w};
#pragma unroll
            for (int kk = 0; kk < 4; kk++) {
                acc[i][0] = fmaf(er[kk], wv[kk].x, acc[i][0]);
                acc[i][1] = fmaf(er[kk], wv[kk].y, acc[i][1]);
                acc[i][2] = fmaf(er[kk], wv[kk].z, acc[i][2]);
                acc[i][3] = fmaf(er[kk], wv[kk].w, acc[i][3]);
            }
        }
    }

    float* dst = (arr == 0) ? g_Uc : (arr == 1) ? g_Vc : (arr == 2) ? g_Ua : g_Va;
    float4 bias = make_float4(0.f, 0.f, 0.f, 0.f);
    if (arr == 0) bias = *reinterpret_cast<const float4*>(cb1 + c0 + cgr * 4);
    if (arr == 2) bias = *reinterpret_cast<const float4*>(ab1 + c0 + cgr * 4);
#pragma unroll
    for (int i = 0; i < 4; i++) {
        float4 o;
        o.x = acc[i][0] + bias.x; o.y = acc[i][1] + bias.y;
        o.z = acc[i][2] + bias.z; o.w = acc[i][3] + bias.w;
        *reinterpret_cast<float4*>(dst + (r0 + rg * 4 + i) * 128 + c0 + cgr * 4) = o;
    }
}

// ---------------- kernel 2: importance head ----------------
__global__ void __launch_bounds__(64) imp_kernel(
    const float* __restrict__ E, const float* __restrict__ trace,
    const float* __restrict__ iW1, const float* __restrict__ ib1,
    const float* __restrict__ iW2, const float* __restrict__ ib2,
    float* __restrict__ outb)
{
    __shared__ float fin[133];
    __shared__ float red2[2];
    int i = blockIdx.x, t = threadIdx.x;
    fin[t] = E[i * 128 + t];
    fin[64 + t] = E[i * 128 + 64 + t];
    if (t < 5) fin[128 + t] = trace[i * 5 + t];
    __syncthreads();
    float acc = ib1[t];
    for (int d = 0; d < 133; d++) acc = fmaf(fin[d], iW1[d * 64 + t], acc);
    float part = gelu_f(acc) * iW2[t];
#pragma unroll
    for (int o = 16; o > 0; o >>= 1) part += __shfl_down_sync(0xffffffffu, part, o);
    if ((t & 31) == 0) red2[t >> 5] = part;
    __syncthreads();
    if (t == 0) outb[i] = sigmoid_f(red2[0] + red2[1] + ib2[0]);
}

// ---------------- fused pair MLP body ----------------
// 512 threads. Phase A: 2 threads/pair (split-K 64). Phase B: ALL 512 threads,
// 2 rows x C cols/thread, 4 col groups.
template <int COLS, bool IS_CONS>
__device__ __forceinline__ void pair_body(
    int bid, float* sm,
    const float* __restrict__ Ug, const float* __restrict__ Vg,
    const float* __restrict__ W2g, const float* __restrict__ b2g,
    const float* __restrict__ w3g, const float* __restrict__ b3g,
    const float* __restrict__ lng, const float* __restrict__ lnb,
    float* __restrict__ outb)
{
    constexpr int C  = COLS / 4;   // cols per thread (16 cons / 8 assoc)
    constexpr int CP = C / 2;      // float2 packs (8 / 4)

    float* Ht   = sm + OFF_HT;
    float* W2s  = sm + OFF_W2;
    float* red  = sm + OFF_RED;
    float* Us   = sm + OFF_US;
    float* Vs   = sm + OFF_VS;
    float* b2s  = sm + OFF_B2;
    float* w3s  = sm + OFF_W3;
    float* lngs = sm + OFF_LNG;
    float* lnbs = sm + OFF_LNB;

    int t = threadIdx.x;

    int rem = bid, ti = 0;
    while (rem >= NT - ti) { rem -= NT - ti; ti++; }
    int tj = ti + rem;
    int I0 = ti * TI, J0 = tj * TI;

    for (int x = t; x < 128 * COLS; x += 512) W2s[x] = W2g[x];
    if (t < COLS) { b2s[t] = b2g[t]; w3s[t] = w3g[t]; }
    if constexpr (IS_CONS) {
        if (t >= 256 && t < 384) { lngs[t - 256] = lng[t - 256]; lnbs[t - 256] = lnb[t - 256]; }
    }
    for (int x = t; x < 32 * 128; x += 512) {
        int r = x >> 7, k = x & 127;
        Us[r * UVS + k] = Ug[(I0 + r) * 128 + k];
        Vs[r * UVS + k] = Vg[(J0 + r) * 128 + k];
    }
    float b3 = b3g[0];
    __syncthreads();

    // phase A decomposition
    int p    = t & 255;
    int half = t >> 8;
    int k0   = half * 64;

    // phase B decomposition: all 512 threads
    int rg = t & 127;   // rows rg*2, rg*2+1
    int cg = t >> 7;    // 4 col groups of C cols

    for (int cch = 0; cch < 4; cch++) {
        const float* u = Us + (cch * 8 + (p >> 5)) * UVS + k0;
        const float* v = Vs + (p & 31) * UVS + k0;

        // ---- phase A ----
        if constexpr (IS_CONS) {
            float4 xv[16];
            float s1 = 0.f, s2 = 0.f;
#pragma unroll
            for (int kk = 0; kk < 16; kk++) {
                float4 uu = *reinterpret_cast<const float4*>(u + kk * 4);
                float4 vv = *reinterpret_cast<const float4*>(v + kk * 4);
                float4 x;
                x.x = uu.x + vv.x; x.y = uu.y + vv.y;
                x.z = uu.z + vv.z; x.w = uu.w + vv.w;
                xv[kk] = x;
                s1 += (x.x + x.y) + (x.z + x.w);
                s2 = fmaf(x.x, x.x, s2); s2 = fmaf(x.y, x.y, s2);
                s2 = fmaf(x.z, x.z, s2); s2 = fmaf(x.w, x.w, s2);
            }
            red[half * 512 + p]       = s1;
            red[half * 512 + 256 + p] = s2;
            __syncthreads();
            float s1t = red[p] + red[512 + p];
            float s2t = red[256 + p] + red[768 + p];
            float mean = s1t * 0.0078125f;
            float var  = s2t * 0.0078125f - mean * mean;
            float rstd = rsqrtf(var + 1e-5f);
#pragma unroll
            for (int kk = 0; kk < 16; kk++) {
                float xs[4] = {xv[kk].x, xv[kk].y, xv[kk].z, xv[kk].w};
#pragma unroll
                for (int i2 = 0; i2 < 4; i2++) {
                    int k = k0 + kk * 4 + i2;
                    float hn = fmaf((xs[i2] - mean) * rstd, lngs[k], lnbs[k]);
                    Ht[k * 256 + p] = gelu_f(hn);
                }
            }
        } else {
#pragma unroll
            for (int kk = 0; kk < 16; kk++) {
                float4 uu = *reinterpret_cast<const float4*>(u + kk * 4);
                float4 vv = *reinterpret_cast<const float4*>(v + kk * 4);
                float xs[4] = {uu.x + vv.x, uu.y + vv.y, uu.z + vv.z, uu.w + vv.w};
#pragma unroll
                for (int i2 = 0; i2 < 4; i2++)
                    Ht[(k0 + kk * 4 + i2) * 256 + p] = fmaxf(xs[i2], 0.f);
            }
        }
        __syncthreads();

        // ---- phase B: 512 threads, 2 rows x C cols each ----
        {
            float2 acc[2][CP];
#pragma unroll
            for (int r = 0; r < 2; r++)
#pragma unroll
                for (int q = 0; q < CP; q++) acc[r][q] = make_float2(0.f, 0.f);

            const float* wbase = W2s + cg * C;
#pragma unroll 2
            for (int k = 0; k < 128; k++) {
                float2 h = *reinterpret_cast<const float2*>(Ht + k * 256 + rg * 2);
                const float4* wp = reinterpret_cast<const float4*>(wbase + k * COLS);
                float2 wv[CP];
#pragma unroll
                for (int q4 = 0; q4 < CP / 2; q4++) {
                    float4 wa = wp[q4];
                    wv[2 * q4]     = make_float2(wa.x, wa.y);
                    wv[2 * q4 + 1] = make_float2(wa.z, wa.w);
                }
                float2 h0 = make_float2(h.x, h.x);
                float2 h1 = make_float2(h.y, h.y);
#pragma unroll
                for (int q = 0; q < CP; q++) {
                    acc[0][q] = ffma2(h0, wv[q], acc[0][q]);
                    acc[1][q] = ffma2(h1, wv[q], acc[1][q]);
                }
            }

            // epilogue: bias + activation + dot(w3) partials
#pragma unroll
            for (int r = 0; r < 2; r++) {
                int row = rg * 2 + r;
                float pr = 0.f;
#pragma unroll
                for (int q = 0; q < CP; q++) {
                    int c0 = cg * C + 2 * q;
                    float y0 = acc[r][q].x + b2s[c0];
                    float y1 = acc[r][q].y + b2s[c0 + 1];
                    if constexpr (IS_CONS) {
                        pr = fmaf(gelu_f(y0), w3s[c0], pr);
                        pr = fmaf(gelu_f(y1), w3s[c0 + 1], pr);
                    } else {
                        pr = fmaf(fmaxf(y0, 0.f), w3s[c0], pr);
                        pr = fmaf(fmaxf(y1, 0.f), w3s[c0 + 1], pr);
                    }
                }
                red[cg * 256 + row] = pr;
            }
        }
        __syncthreads();

        // ---- final reduce + sigmoid + triu-packed store ----
        if (t < 256) {
            float logit = b3 + ((red[t] + red[256 + t]) + (red[512 + t] + red[768 + t]));
            int i = I0 + cch * 8 + (t >> 5), j = J0 + (t & 31);
            if (i < j) {
                int pidx = i * (N_ - 1) - (i * (i - 1)) / 2 + (j - i - 1);
                outb[pidx] = sigmoid_f(logit);
            }
        }
        __syncthreads();
    }
}

// ---------------- fused kernel ----------------
__global__ void __launch_bounds__(512, 1) pair_fused_kernel(
    const float* __restrict__ cW2, const float* __restrict__ cb2,
    const float* __restrict__ cW3, const float* __restrict__ cb3,
    const float* __restrict__ lng, const float* __restrict__ lnb,
    const float* __restrict__ aW2, const float* __restrict__ ab2,
    const float* __restrict__ aW3, const float* __restrict__ ab3,
    float* __restrict__ outb)
{
    extern __shared__ float sm[];
    if (blockIdx.x < NBLK) {
        pair_body<64, true>(blockIdx.x, sm, g_Uc, g_Vc, cW2, cb2, cW3, cb3, lng, lnb, outb);
    } else {
        pair_body<32, false>(blockIdx.x - NBLK, sm, g_Ua, g_Va, aW2, ab2, aW3, ab3,
                             nullptr, nullptr, outb + P_);
    }
}

// ---------------- launch ----------------
extern "C" void kernel_launch(void* const* d_in, const int* in_sizes, int n_in,
                              void* d_out, int out_size)
{
    const float* E     = (const float*)d_in[0];
    const float* trace = (const float*)d_in[1];
    const float* cW1 = (const float*)d_in[2];
    const float* cb1 = (const float*)d_in[3];
    const float* lng = (const float*)d_in[4];
    const float* lnb = (const float*)d_in[5];
    const float* cW2 = (const float*)d_in[6];
    const float* cb2 = (const float*)d_in[7];
    const float* cW3 = (const float*)d_in[8];
    const float* cb3 = (const float*)d_in[9];
    const float* aW1 = (const float*)d_in[10];
    const float* ab1 = (const float*)d_in[11];
    const float* aW2 = (const float*)d_in[12];
    const float* ab2 = (const float*)d_in[13];
    const float* aW3 = (const float*)d_in[14];
    const float* ab3 = (const float*)d_in[15];
    const float* iW1 = (const float*)d_in[16];
    const float* ib1 = (const float*)d_in[17];
    const float* iW2 = (const float*)d_in[18];
    const float* ib2 = (const float*)d_in[19];
    float* out = (float*)d_out;

    cudaFuncSetAttribute(precompute_gemm_kernel, cudaFuncAttributeMaxDynamicSharedMemorySize, PRE_SMEM_BYTES);
    cudaFuncSetAttribute(pair_fused_kernel, cudaFuncAttributeMaxDynamicSharedMemorySize, SMEM_BYTES);

    precompute_gemm_kernel<<<128, 256, PRE_SMEM_BYTES>>>(E, cW1, cb1, aW1, ab1);
    imp_kernel<<<N_, 64>>>(E, trace, iW1, ib1, iW2, ib2, out + 2 * P_);
    pair_fused_kernel<<<2 * NBLK, 512, SMEM_BYTES>>>(
        cW2, cb2, cW3, cb3, lng, lnb, aW2, ab2, aW3, ab3, out);
}

// round 6
// speedup vs baseline: 2.7613x; 2.0141x over previous
#include <cuda_runtime.h>
#include <cuda_fp16.h>
#include <math.h>
#include <stdint.h>

// ---------------- problem constants ----------------
constexpr int N_ = 1024;
constexpr int H_ = 128;
constexpr int P_ = 523776;          // N*(N-1)/2
constexpr int TI = 32;              // pair tile dim
constexpr int NT = N_ / TI;         // 32 tiles per dim
constexpr int NBLK = NT * (NT + 1) / 2;  // 528 blocks over upper triangle
constexpr int UVS = 132;            // padded row stride for Us/Vs (float4, conflict-free)

// pair-kernel smem layout
// bytes [0, 65536):        Ht fp16 [256 rows][256 B] (16B chunks, XOR swizzle)
// bytes [65536, 81920):    Wt fp16 [COLS rows][256 B] (same swizzle)
// floats from 20480:
constexpr int OFF_RED = 20480;               // [1024]
constexpr int OFF_US  = OFF_RED + 1024;      // [32][132]
constexpr int OFF_VS  = OFF_US + 32 * UVS;   // [32][132]
constexpr int OFF_B2  = OFF_VS + 32 * UVS;   // [64]
constexpr int OFF_W3  = OFF_B2 + 64;         // [64]
constexpr int OFF_LNG = OFF_W3 + 64;         // [128]
constexpr int OFF_LNB = OFF_LNG + 128;       // [128]
constexpr int SMEM_FLOATS = OFF_LNB + 128;
constexpr int SMEM_BYTES = SMEM_FLOATS * 4;  // ~121 KB

// precompute-kernel smem
constexpr int PRE_ES_STRIDE = 132;
constexpr int PRE_WS_STRIDE = 68;
constexpr int PRE_OFF_WS = 64 * PRE_ES_STRIDE;
constexpr int PRE_SMEM_BYTES = (PRE_OFF_WS + 128 * PRE_WS_STRIDE) * 4;

// ---------------- device scratch ----------------
__device__ float g_Uc[N_ * H_];
__device__ float g_Vc[N_ * H_];
__device__ float g_Ua[N_ * H_];
__device__ float g_Va[N_ * H_];

// ---------------- helpers ----------------
__device__ __forceinline__ float gelu_f(float x) {
    return 0.5f * x * (1.0f + erff(x * 0.70710678118654752440f));
}
__device__ __forceinline__ float sigmoid_f(float x) {
    return 1.0f / (1.0f + expf(-x));
}
__device__ __forceinline__ uint32_t smem_u32(const void* p) {
    uint32_t a;
    asm("{ .reg .u64 t; cvta.to.shared.u64 t, %1; cvt.u32.u64 %0, t; }" : "=r"(a) : "l"(p));
    return a;
}
__device__ __forceinline__ void ldsm_x4(uint32_t& r0, uint32_t& r1, uint32_t& r2, uint32_t& r3,
                                        uint32_t addr) {
    asm volatile("ldmatrix.sync.aligned.m8n8.x4.shared.b16 {%0,%1,%2,%3}, [%4];"
                 : "=r"(r0), "=r"(r1), "=r"(r2), "=r"(r3) : "r"(addr));
}
__device__ __forceinline__ void ldsm_x2(uint32_t& r0, uint32_t& r1, uint32_t addr) {
    asm volatile("ldmatrix.sync.aligned.m8n8.x2.shared.b16 {%0,%1}, [%2];"
                 : "=r"(r0), "=r"(r1) : "r"(addr));
}
__device__ __forceinline__ void mma16816(float* c, uint32_t a0, uint32_t a1, uint32_t a2,
                                         uint32_t a3, uint32_t b0, uint32_t b1) {
    asm volatile(
        "mma.sync.aligned.m16n8k16.row.col.f32.f16.f16.f32 "
        "{%0,%1,%2,%3}, {%4,%5,%6,%7}, {%8,%9}, {%0,%1,%2,%3};"
        : "+f"(c[0]), "+f"(c[1]), "+f"(c[2]), "+f"(c[3])
        : "r"(a0), "r"(a1), "r"(a2), "r"(a3), "r"(b0), "r"(b1));
}
// pack 8 floats -> uint4 of fp16
__device__ __forceinline__ uint4 pack8h(const float* h) {
    __half2 p0 = __floats2half2_rn(h[0], h[1]);
    __half2 p1 = __floats2half2_rn(h[2], h[3]);
    __half2 p2 = __floats2half2_rn(h[4], h[5]);
    __half2 p3 = __floats2half2_rn(h[6], h[7]);
    uint4 r;
    r.x = *reinterpret_cast<uint32_t*>(&p0);
    r.y = *reinterpret_cast<uint32_t*>(&p1);
    r.z = *reinterpret_cast<uint32_t*>(&p2);
    r.w = *reinterpret_cast<uint32_t*>(&p3);
    return r;
}

// ---------------- kernel 1: precompute as tiled GEMM ----------------
__global__ void __launch_bounds__(256) precompute_gemm_kernel(
    const float* __restrict__ E,
    const float* __restrict__ cW1, const float* __restrict__ cb1,
    const float* __restrict__ aW1, const float* __restrict__ ab1)
{
    extern __shared__ float psm[];
    float* Es = psm;
    float* Ws = psm + PRE_OFF_WS;

    int rowTile = blockIdx.x >> 3;
    int colTile = blockIdx.x & 7;
    int arr = colTile >> 1;
    int c0 = (colTile & 1) * 64;
    int r0 = rowTile * 64;

    const float* Wsrc = (arr < 2) ? cW1 : aW1;
    int doff = (arr & 1) ? 128 : 0;

    int t = threadIdx.x;
    for (int x = t; x < 64 * 32; x += 256) {
        int r = x >> 5, k4 = x & 31;
        float4 e = *reinterpret_cast<const float4*>(E + (r0 + r) * 128 + k4 * 4);
        *reinterpret_cast<float4*>(Es + r * PRE_ES_STRIDE + k4 * 4) = e;
    }
    for (int x = t; x < 128 * 16; x += 256) {
        int d = x >> 4, c4 = x & 15;
        float4 w = *reinterpret_cast<const float4*>(Wsrc + (doff + d) * 128 + c0 + c4 * 4);
        *reinterpret_cast<float4*>(Ws + d * PRE_WS_STRIDE + c4 * 4) = w;
    }
    __syncthreads();

    int cgr = t & 15;
    int rg  = t >> 4;
    float acc[4][4] = {};

#pragma unroll 4
    for (int k = 0; k < 128; k += 4) {
        float4 ev[4], wv[4];
#pragma unroll
        for (int i = 0; i < 4; i++)
            ev[i] = *reinterpret_cast<const float4*>(Es + (rg * 4 + i) * PRE_ES_STRIDE + k);
#pragma unroll
        for (int kk = 0; kk < 4; kk++)
            wv[kk] = *reinterpret_cast<const float4*>(Ws + (k + kk) * PRE_WS_STRIDE + cgr * 4);
#pragma unroll
        for (int i = 0; i < 4; i++) {
            float er[4] = {ev[i].x, ev[i].y, ev[i].z, ev[i].w};
#pragma unroll
            for (int kk = 0; kk < 4; kk++) {
                acc[i][0] = fmaf(er[kk], wv[kk].x, acc[i][0]);
                acc[i][1] = fmaf(er[kk], wv[kk].y, acc[i][1]);
                acc[i][2] = fmaf(er[kk], wv[kk].z, acc[i][2]);
                acc[i][3] = fmaf(er[kk], wv[kk].w, acc[i][3]);
            }
        }
    }

    float* dst = (arr == 0) ? g_Uc : (arr == 1) ? g_Vc : (arr == 2) ? g_Ua : g_Va;
    float4 bias = make_float4(0.f, 0.f, 0.f, 0.f);
    if (arr == 0) bias = *reinterpret_cast<const float4*>(cb1 + c0 + cgr * 4);
    if (arr == 2) bias = *reinterpret_cast<const float4*>(ab1 + c0 + cgr * 4);
#pragma unroll
    for (int i = 0; i < 4; i++) {
        float4 o;
        o.x = acc[i][0] + bias.x; o.y = acc[i][1] + bias.y;
        o.z = acc[i][2] + bias.z; o.w = acc[i][3] + bias.w;
        *reinterpret_cast<float4*>(dst + (r0 + rg * 4 + i) * 128 + c0 + cgr * 4) = o;
    }
}

// ---------------- kernel 2: importance head ----------------
__global__ void __launch_bounds__(64) imp_kernel(
    const float* __restrict__ E, const float* __restrict__ trace,
    const float* __restrict__ iW1, const float* __restrict__ ib1,
    const float* __restrict__ iW2, const float* __restrict__ ib2,
    float* __restrict__ outb)
{
    __shared__ float fin[133];
    __shared__ float red2[2];
    int i = blockIdx.x, t = threadIdx.x;
    fin[t] = E[i * 128 + t];
    fin[64 + t] = E[i * 128 + 64 + t];
    if (t < 5) fin[128 + t] = trace[i * 5 + t];
    __syncthreads();
    float acc = ib1[t];
    for (int d = 0; d < 133; d++) acc = fmaf(fin[d], iW1[d * 64 + t], acc);
    float part = gelu_f(acc) * iW2[t];
#pragma unroll
    for (int o = 16; o > 0; o >>= 1) part += __shfl_down_sync(0xffffffffu, part, o);
    if ((t & 31) == 0) red2[t >> 5] = part;
    __syncthreads();
    if (t == 0) outb[i] = sigmoid_f(red2[0] + red2[1] + ib2[0]);
}

// ---------------- fused pair MLP body (mma.sync phase B) ----------------
// 512 threads. Phase A: 2 threads/pair write fp16 Ht (swizzled 16B chunks).
// Phase B: 16 warps, warp tile M=64 x N=COLS/4, B fragments register-resident.
template <int COLS, bool IS_CONS>
__device__ __forceinline__ void pair_body(
    int bid, float* sm,
    const float* __restrict__ Ug, const float* __restrict__ Vg,
    const float* __restrict__ W2g, const float* __restrict__ b2g,
    const float* __restrict__ w3g, const float* __restrict__ b3g,
    const float* __restrict__ lng, const float* __restrict__ lnb,
    float* __restrict__ outb)
{
    constexpr int NW = COLS / 4;       // cols per warp (16 / 8)
    constexpr int NTL = NW / 8;        // n-tiles per warp (2 / 1)

    float* red  = sm + OFF_RED;
    float* Us   = sm + OFF_US;
    float* Vs   = sm + OFF_VS;
    float* b2s  = sm + OFF_B2;
    float* w3s  = sm + OFF_W3;
    float* lngs = sm + OFF_LNG;
    float* lnbs = sm + OFF_LNB;
    char*  smc  = reinterpret_cast<char*>(sm);
    uint32_t base_u32 = smem_u32(sm);
    uint32_t WBASE = base_u32 + 65536;

    int t = threadIdx.x;
    int wid = t >> 5;
    int lane = t & 31;

    // decode bid -> (ti, tj), tj >= ti
    int rem = bid, ti = 0;
    while (rem >= NT - ti) { rem -= NT - ti; ti++; }
    int tj = ti + rem;
    int I0 = ti * TI, J0 = tj * TI;

    // ---- one-time smem fills ----
    // Wt fp16: [COLS rows][128 k], 16B chunks, chunk' = j ^ (n&7)
    for (int x = t; x < COLS * 16; x += 512) {
        int n = x >> 4, j = x & 15;
        float w[8];
#pragma unroll
        for (int kk = 0; kk < 8; kk++) w[kk] = W2g[(j * 8 + kk) * COLS + n];
        uint4 pk = pack8h(w);
        *reinterpret_cast<uint4*>(smc + 65536 + n * 256 + ((j ^ (n & 7)) << 4)) = pk;
    }
    if (t < COLS) { b2s[t] = b2g[t]; w3s[t] = w3g[t]; }
    if constexpr (IS_CONS) {
        if (t >= 256 && t < 384) { lngs[t - 256] = lng[t - 256]; lnbs[t - 256] = lnb[t - 256]; }
    }
    for (int x = t; x < 32 * 128; x += 512) {
        int r = x >> 7, k = x & 127;
        Us[r * UVS + k] = Ug[(I0 + r) * 128 + k];
        Vs[r * UVS + k] = Vg[(J0 + r) * 128 + k];
    }
    float b3 = b3g[0];
    __syncthreads();

    // ---- warp GEMM decomposition ----
    int mrange = wid & 3;                 // 4 m-ranges of 64 rows
    int nrange = wid >> 2;                // 4 n-ranges of NW cols
    int m0 = mrange * 64;
    int n0 = nrange * NW;
    int g = lane >> 2, tid4 = lane & 3;

    // B fragments: register-resident for the whole CTA lifetime
    uint32_t bfr[8][2 * NTL];
    {
        if constexpr (NTL == 2) {
            int nb = n0 + ((lane >> 4) & 1) * 8 + (lane & 7);
#pragma unroll
            for (int s = 0; s < 8; s++) {
                uint32_t addr = WBASE + nb * 256 +
                                (((2 * s + ((lane >> 3) & 1)) ^ (lane & 7)) << 4);
                ldsm_x4(bfr[s][0], bfr[s][1], bfr[s][2], bfr[s][3], addr);
            }
        } else {
            int nb = n0 + (lane & 7);
#pragma unroll
            for (int s = 0; s < 8; s++) {
                uint32_t addr = WBASE + nb * 256 +
                                (((2 * s + ((lane >> 3) & 1)) ^ (lane & 7)) << 4);
                ldsm_x2(bfr[s][0], bfr[s][1], addr);
            }
        }
    }

    // A ldmatrix lane geometry (row low bits fixed per lane)
    int roff = ((lane >> 3) & 1) * 8 + (lane & 7);
    uint32_t a_row_base = base_u32 + (m0 + roff) * 256;
    uint32_t a_sw[8];
#pragma unroll
    for (int s = 0; s < 8; s++)
        a_sw[s] = (uint32_t)(((2 * s + (lane >> 4)) ^ (lane & 7)) << 4);

    // phase A decomposition
    int p    = t & 255;
    int half = t >> 8;
    int k0   = half * 64;
    uint32_t st_base = (uint32_t)(p * 256);
    const float* vrow = Vs + (p & 31) * UVS + k0;

    for (int cch = 0; cch < 4; cch++) {
        const float* urow = Us + (cch * 8 + (p >> 5)) * UVS + k0;

        // ---- phase A: hidden vector -> fp16 Ht ----
        if constexpr (IS_CONS) {
            float s1 = 0.f, s2 = 0.f;
#pragma unroll
            for (int kk = 0; kk < 16; kk++) {
                float4 uu = *reinterpret_cast<const float4*>(urow + kk * 4);
                float4 vv = *reinterpret_cast<const float4*>(vrow + kk * 4);
                float x0 = uu.x + vv.x, x1 = uu.y + vv.y;
                float x2 = uu.z + vv.z, x3 = uu.w + vv.w;
                s1 += (x0 + x1) + (x2 + x3);
                s2 = fmaf(x0, x0, s2); s2 = fmaf(x1, x1, s2);
                s2 = fmaf(x2, x2, s2); s2 = fmaf(x3, x3, s2);
            }
            red[half * 512 + p]       = s1;
            red[half * 512 + 256 + p] = s2;
            __syncthreads();
            float s1t = red[p] + red[512 + p];
            float s2t = red[256 + p] + red[768 + p];
            float mean = s1t * 0.0078125f;
            float var  = s2t * 0.0078125f - mean * mean;
            float rstd = rsqrtf(var + 1e-5f);
#pragma unroll
            for (int j = 0; j < 8; j++) {
                float4 uu0 = *reinterpret_cast<const float4*>(urow + j * 8);
                float4 vv0 = *reinterpret_cast<const float4*>(vrow + j * 8);
                float4 uu1 = *reinterpret_cast<const float4*>(urow + j * 8 + 4);
                float4 vv1 = *reinterpret_cast<const float4*>(vrow + j * 8 + 4);
                float xs[8] = {uu0.x + vv0.x, uu0.y + vv0.y, uu0.z + vv0.z, uu0.w + vv0.w,
                               uu1.x + vv1.x, uu1.y + vv1.y, uu1.z + vv1.z, uu1.w + vv1.w};
                float hs[8];
#pragma unroll
                for (int i2 = 0; i2 < 8; i2++) {
                    int k = k0 + j * 8 + i2;
                    float hn = fmaf((xs[i2] - mean) * rstd, lngs[k], lnbs[k]);
                    hs[i2] = gelu_f(hn);
                }
                uint4 pk = pack8h(hs);
                *reinterpret_cast<uint4*>(
                    smc + st_base + (((half * 8 + j) ^ (p & 7)) << 4)) = pk;
            }
        } else {
#pragma unroll
            for (int j = 0; j < 8; j++) {
                float4 uu0 = *reinterpret_cast<const float4*>(urow + j * 8);
                float4 vv0 = *reinterpret_cast<const float4*>(vrow + j * 8);
                float4 uu1 = *reinterpret_cast<const float4*>(urow + j * 8 + 4);
                float4 vv1 = *reinterpret_cast<const float4*>(vrow + j * 8 + 4);
                float hs[8] = {fmaxf(uu0.x + vv0.x, 0.f), fmaxf(uu0.y + vv0.y, 0.f),
                               fmaxf(uu0.z + vv0.z, 0.f), fmaxf(uu0.w + vv0.w, 0.f),
                               fmaxf(uu1.x + vv1.x, 0.f), fmaxf(uu1.y + vv1.y, 0.f),
                               fmaxf(uu1.z + vv1.z, 0.f), fmaxf(uu1.w + vv1.w, 0.f)};
                uint4 pk = pack8h(hs);
                *reinterpret_cast<uint4*>(
                    smc + st_base + (((half * 8 + j) ^ (p & 7)) << 4)) = pk;
            }
        }
        __syncthreads();

        // ---- phase B: mma.sync GEMM ----
        float acc[4][NTL][4];
#pragma unroll
        for (int mt = 0; mt < 4; mt++)
#pragma unroll
            for (int nt = 0; nt < NTL; nt++)
#pragma unroll
                for (int q = 0; q < 4; q++) acc[mt][nt][q] = 0.f;

#pragma unroll
        for (int s = 0; s < 8; s++) {
#pragma unroll
            for (int mt = 0; mt < 4; mt++) {
                uint32_t a0, a1, a2, a3;
                ldsm_x4(a0, a1, a2, a3, a_row_base + mt * 4096 + a_sw[s]);
                mma16816(acc[mt][0], a0, a1, a2, a3, bfr[s][0], bfr[s][1]);
                if constexpr (NTL == 2)
                    mma16816(acc[mt][1], a0, a1, a2, a3, bfr[s][2], bfr[s][3]);
            }
        }

        // ---- epilogue: bias + act + w3 dot, quad reduce, smem partials ----
#pragma unroll
        for (int mt = 0; mt < 4; mt++) {
            float pr0 = 0.f, pr1 = 0.f;
#pragma unroll
            for (int nt = 0; nt < NTL; nt++) {
                int c0 = n0 + nt * 8 + 2 * tid4;
                float w30 = w3s[c0], w31 = w3s[c0 + 1];
                float bb0 = b2s[c0], bb1 = b2s[c0 + 1];
                float y00 = acc[mt][nt][0] + bb0;
                float y01 = acc[mt][nt][1] + bb1;
                float y10 = acc[mt][nt][2] + bb0;
                float y11 = acc[mt][nt][3] + bb1;
                if constexpr (IS_CONS) {
                    pr0 = fmaf(gelu_f(y00), w30, pr0);
                    pr0 = fmaf(gelu_f(y01), w31, pr0);
                    pr1 = fmaf(gelu_f(y10), w30, pr1);
                    pr1 = fmaf(gelu_f(y11), w31, pr1);
                } else {
                    pr0 = fmaf(fmaxf(y00, 0.f), w30, pr0);
                    pr0 = fmaf(fmaxf(y01, 0.f), w31, pr0);
                    pr1 = fmaf(fmaxf(y10, 0.f), w30, pr1);
                    pr1 = fmaf(fmaxf(y11, 0.f), w31, pr1);
                }
            }
            pr0 += __shfl_xor_sync(0xffffffffu, pr0, 1);
            pr0 += __shfl_xor_sync(0xffffffffu, pr0, 2);
            pr1 += __shfl_xor_sync(0xffffffffu, pr1, 1);
            pr1 += __shfl_xor_sync(0xffffffffu, pr1, 2);
            if (tid4 == 0) {
                red[nrange * 256 + m0 + mt * 16 + g]     = pr0;
                red[nrange * 256 + m0 + mt * 16 + 8 + g] = pr1;
            }
        }
        __syncthreads();

        // ---- final: combine 4 n-ranges + sigmoid + triu-packed store ----
        if (t < 256) {
            float logit = b3 + ((red[t] + red[256 + t]) + (red[512 + t] + red[768 + t]));
            int i = I0 + cch * 8 + (t >> 5), j = J0 + (t & 31);
            if (i < j) {
                int pidx = i * (N_ - 1) - (i * (i - 1)) / 2 + (j - i - 1);
                outb[pidx] = sigmoid_f(logit);
            }
        }
        __syncthreads();   // red/Ht free for next chunk
    }
}

// ---------------- fused kernel ----------------
__global__ void __launch_bounds__(512, 1) pair_fused_kernel(
    const float* __restrict__ cW2, const float* __restrict__ cb2,
    const float* __restrict__ cW3, const float* __restrict__ cb3,
    const float* __restrict__ lng, const float* __restrict__ lnb,
    const float* __restrict__ aW2, const float* __restrict__ ab2,
    const float* __restrict__ aW3, const float* __restrict__ ab3,
    float* __restrict__ outb)
{
    extern __shared__ float sm[];
    if (blockIdx.x < NBLK) {
        pair_body<64, true>(blockIdx.x, sm, g_Uc, g_Vc, cW2, cb2, cW3, cb3, lng, lnb, outb);
    } else {
        pair_body<32, false>(blockIdx.x - NBLK, sm, g_Ua, g_Va, aW2, ab2, aW3, ab3,
                             nullptr, nullptr, outb + P_);
    }
}

// ---------------- launch ----------------
extern "C" void kernel_launch(void* const* d_in, const int* in_sizes, int n_in,
                              void* d_out, int out_size)
{
    const float* E     = (const float*)d_in[0];
    const float* trace = (const float*)d_in[1];
    const float* cW1 = (const float*)d_in[2];
    const float* cb1 = (const float*)d_in[3];
    const float* lng = (const float*)d_in[4];
    const float* lnb = (const float*)d_in[5];
    const float* cW2 = (const float*)d_in[6];
    const float* cb2 = (const float*)d_in[7];
    const float* cW3 = (const float*)d_in[8];
    const float* cb3 = (const float*)d_in[9];
    const float* aW1 = (const float*)d_in[10];
    const float* ab1 = (const float*)d_in[11];
    const float* aW2 = (const float*)d_in[12];
    const float* ab2 = (const float*)d_in[13];
    const float* aW3 = (const float*)d_in[14];
    const float* ab3 = (const float*)d_in[15];
    const float* iW1 = (const float*)d_in[16];
    const float* ib1 = (const float*)d_in[17];
    const float* iW2 = (const float*)d_in[18];
    const float* ib2 = (const float*)d_in[19];
    float* out = (float*)d_out;

    cudaFuncSetAttribute(precompute_gemm_kernel, cudaFuncAttributeMaxDynamicSharedMemorySize, PRE_SMEM_BYTES);
    cudaFuncSetAttribute(pair_fused_kernel, cudaFuncAttributeMaxDynamicSharedMemorySize, SMEM_BYTES);

    precompute_gemm_kernel<<<128, 256, PRE_SMEM_BYTES>>>(E, cW1, cb1, aW1, ab1);
    imp_kernel<<<N_, 64>>>(E, trace, iW1, ib1, iW2, ib2, out + 2 * P_);
    pair_fused_kernel<<<2 * NBLK, 512, SMEM_BYTES>>>(
        cW2, cb2, cW3, cb3, lng, lnb, aW2, ab2, aW3, ab3, out);
}